// round 15
// baseline (speedup 1.0000x reference)
#include <cuda_runtime.h>
#include <cuda_fp16.h>
#include <cstdint>
#include <cstddef>

// FusedAGGemm round 15: A fp32->fp16 conversion fused INTO the GEMM via
// producer/consumer flags (all 256 CTAs co-resident). W prep separate (9us).
//   C[M,N] = sum_r A_r[M,KLOC] @ W[r*KLOC:(r+1)*KLOC] + bias

#define MDIM 4096
#define KLOC 1024
#define KDIM 8192
#define NDIM 1024
#define BM 128
#define BN 128
#define BK 64
#define NTH 256
#define NTILES (KDIM / BK)    // 128
#define NSTAGE 3

#define SWZ(o) ((o) ^ (((o) >> 3) & 0x70))
#define STAGE_BYTES 32768
#define SM_A(s) ((s) * STAGE_BYTES)
#define SM_B(s) ((s) * STAGE_BYTES + 16384)
#define SMEM_TOTAL (NSTAGE * STAGE_BYTES)

__device__ __half g_At[(size_t)MDIM * KDIM];
__device__ __half g_Wt[(size_t)NDIM * KDIM];
__device__ unsigned g_aflag[32][8];

__device__ __forceinline__ uint32_t smem_u32(const void* p) {
    uint32_t a;
    asm("{ .reg .u64 t; cvta.to.shared.u64 t, %1; cvt.u32.u64 %0, t; }"
        : "=r"(a) : "l"(p));
    return a;
}
__device__ __forceinline__ uint32_t f16x2(float lo, float hi) {
    uint32_t r;
    asm("cvt.rn.f16x2.f32 %0, %2, %1;" : "=r"(r) : "f"(lo), "f"(hi));
    return r;
}
__device__ __forceinline__ void cp_async16(uint32_t dst, const void* src) {
    asm volatile("cp.async.cg.shared.global [%0], [%1], 16;"
                 :: "r"(dst), "l"(src) : "memory");
}
__device__ __forceinline__ void ldsm4(uint32_t addr, uint32_t* r) {
    asm volatile("ldmatrix.sync.aligned.m8n8.x4.shared.b16 {%0,%1,%2,%3}, [%4];"
                 : "=r"(r[0]), "=r"(r[1]), "=r"(r[2]), "=r"(r[3]) : "r"(addr));
}
__device__ __forceinline__ void mma_f16(float* c, const uint32_t* a,
                                        uint32_t b0, uint32_t b1) {
    asm volatile(
        "mma.sync.aligned.m16n8k16.row.col.f32.f16.f16.f32 "
        "{%0,%1,%2,%3}, {%4,%5,%6,%7}, {%8,%9}, {%0,%1,%2,%3};"
        : "+f"(c[0]), "+f"(c[1]), "+f"(c[2]), "+f"(c[3])
        : "r"(a[0]), "r"(a[1]), "r"(a[2]), "r"(a[3]), "r"(b0), "r"(b1));
}
__device__ __forceinline__ void cvt8(const float* s, __half* d) {
    float4 v0 = *reinterpret_cast<const float4*>(s);
    float4 v1 = *reinterpret_cast<const float4*>(s + 4);
    uint4 o;
    o.x = f16x2(v0.x, v0.y); o.y = f16x2(v0.z, v0.w);
    o.z = f16x2(v1.x, v1.y); o.w = f16x2(v1.z, v1.w);
    *reinterpret_cast<uint4*>(d) = o;
}

__global__ void init_flags() {
    reinterpret_cast<unsigned*>(g_aflag)[threadIdx.x] = 0u;   // 256 words
}

__global__ void prep_W(const float* __restrict__ W) {
    __shared__ float t[32][33];
    const int n0 = blockIdx.x * 32, k0 = blockIdx.y * 32;
    const int tx = threadIdx.x, ty = threadIdx.y;
    #pragma unroll
    for (int j = 0; j < 4; ++j)
        t[ty + 8 * j][tx] = W[(size_t)(k0 + ty + 8 * j) * NDIM + n0 + tx];
    __syncthreads();
    #pragma unroll
    for (int j = 0; j < 4; ++j)
        g_Wt[(size_t)(n0 + ty + 8 * j) * KDIM + k0 + tx] =
            __float2half_rn(t[tx][ty + 8 * j]);
}

__global__ __launch_bounds__(NTH, 2)
void ag_gemm_fused(const float* __restrict__ A,
                   const float* __restrict__ bias, float* __restrict__ C)
{
    extern __shared__ char smem[];
    const uint32_t sb = smem_u32(smem);
    const int tid = threadIdx.x;
    const int wid = tid >> 5, lane = tid & 31;
    const int wm = wid >> 2, wn = wid & 3;
    const int nb = blockIdx.x;          // n-block AND owned k-chunk
    const int mb = blockIdx.y;
    const int m0 = mb * BM, n0 = nb * BN;

    // ---- upfront: cooperative convert of chunk 0 (shard 0) for this row ----
    for (int i = tid; i < 2048; i += NTH) {        // 16 rows x 128 groups of 8
        int rr = nb * 16 + (i >> 7);
        int cc = (i & 127) * 8;
        cvt8(A + (size_t)(m0 + rr) * KLOC + cc,
             g_At + (size_t)(m0 + rr) * KDIM + cc);
    }
    __threadfence();
    __syncthreads();
    if (tid == 0) {
        atomicAdd(&g_aflag[mb][0], 1u);
        while (atomicAdd(&g_aflag[mb][0], 0u) < 8u) {}
    }
    __syncthreads();

    // ---- lazy conversion state: chunk nb (shard nb), 64 slices ----
    const float* asrc = A + ((size_t)nb * MDIM + m0 + (tid >> 7)) * KLOC
                        + (tid & 127) * 8;
    __half* adst = g_At + (size_t)(m0 + (tid >> 7)) * KDIM + nb * KLOC
                   + (tid & 127) * 8;
    int rem = (nb == 0) ? 0 : 64;
    const int cpi = (nb == 0) ? 0 : (nb == 1) ? 7 : (nb == 2) ? 3
                     : (nb <= 4) ? 2 : 1;
    bool announced = (nb == 0);

    const uint32_t rowA = (uint32_t)(wm * 64 + (lane & 15));
    const uint32_t kA16 = (uint32_t)((lane >> 4) * 16);
    const uint32_t rowB = (uint32_t)(wn * 32 + (lane & 7) + ((lane >> 4) << 3));
    const uint32_t kB16 = (uint32_t)(((lane >> 3) & 1) * 16);

    float acc[4][4][4];
    #pragma unroll
    for (int i = 0; i < 4; ++i)
        #pragma unroll
        for (int j = 0; j < 4; ++j)
            #pragma unroll
            for (int q = 0; q < 4; ++q) acc[i][j][q] = 0.0f;

    const int grow = tid >> 3;
    const int gcol = tid & 7;

    auto issue_tile = [&](int kt, int s) {
        const __half* Ab = g_At + (size_t)(m0 + grow) * KDIM + kt * BK + gcol * 8;
        const __half* Bb = g_Wt + (size_t)(n0 + grow) * KDIM + kt * BK + gcol * 8;
        #pragma unroll
        for (int i = 0; i < 4; ++i) {
            uint32_t o = SWZ((uint32_t)(grow + 32 * i) * 128u + (uint32_t)gcol * 16u);
            cp_async16(sb + SM_A(s) + o, Ab + (size_t)i * 32 * KDIM);
            cp_async16(sb + SM_B(s) + o, Bb + (size_t)i * 32 * KDIM);
        }
        asm volatile("cp.async.commit_group;" ::: "memory");
    };

    auto compute_tile = [&](int s) {
        #pragma unroll
        for (int k16 = 0; k16 < 4; ++k16) {
            uint32_t a[4][4], b[2][4];
            #pragma unroll
            for (int i = 0; i < 4; ++i) {
                uint32_t o = (rowA + 16u * i) * 128u + (uint32_t)k16 * 32u + kA16;
                ldsm4(sb + SM_A(s) + SWZ(o), a[i]);
            }
            #pragma unroll
            for (int j = 0; j < 2; ++j) {
                uint32_t o = (rowB + 16u * j) * 128u + (uint32_t)k16 * 32u + kB16;
                ldsm4(sb + SM_B(s) + SWZ(o), b[j]);
            }
            #pragma unroll
            for (int i = 0; i < 4; ++i) {
                #pragma unroll
                for (int jj = 0; jj < 4; ++jj)
                    mma_f16(acc[i][jj], a[i],
                            b[jj >> 1][(jj & 1) * 2], b[jj >> 1][(jj & 1) * 2 + 1]);
            }
        }
    };

    issue_tile(0, 0);
    issue_tile(1, 1);

    for (int kt = 0; kt < NTILES; ++kt) {
        const int s = kt % NSTAGE;
        const int nk = kt + 2;
        if (nk < NTILES) {
            if ((nk & 15) == 0) {                    // new chunk boundary
                if (tid == 0) {
                    volatile unsigned* f =
                        &reinterpret_cast<unsigned*>(g_aflag)[mb * 8 + (nk >> 4)];
                    while (*f == 0u) {}
                }
                __syncthreads();
            }
            issue_tile(nk, nk % NSTAGE);
            asm volatile("cp.async.wait_group 2;" ::: "memory");
        } else {
            asm volatile("cp.async.wait_group 0;" ::: "memory");
        }
        __syncthreads();

        if (!announced && rem == 0) {                // publish owned chunk
            if (tid == 0)
                *(volatile unsigned*)&g_aflag[mb][nb] = 1u;
            announced = true;
        }
        if (rem > 0) {                               // lazy conversion slices
            int n = rem < cpi ? rem : cpi;
            for (int j = 0; j < n; ++j) {
                cvt8(asrc, adst);
                asrc += 2 * KLOC;
                adst += 2 * KDIM;
            }
            rem -= n;
            if (rem == 0) __threadfence();
        }

        compute_tile(s);
        __syncthreads();
    }

    // ---- epilogue ----
    const int er = lane >> 2;
    const int ec = (lane & 3) * 2;
    #pragma unroll
    for (int i = 0; i < 4; ++i) {
        const int gm = m0 + wm * 64 + i * 16 + er;
        #pragma unroll
        for (int jj = 0; jj < 4; ++jj) {
            const int gn = n0 + wn * 32 + jj * 8 + ec;
            const float bx = __ldg(bias + gn);
            const float by = __ldg(bias + gn + 1);
            float2 o0 = { acc[i][jj][0] + bx, acc[i][jj][1] + by };
            float2 o1 = { acc[i][jj][2] + bx, acc[i][jj][3] + by };
            *reinterpret_cast<float2*>(C + (size_t)gm * NDIM + gn) = o0;
            *reinterpret_cast<float2*>(C + (size_t)(gm + 8) * NDIM + gn) = o1;
        }
    }
}

extern "C" void kernel_launch(void* const* d_in, const int* in_sizes, int n_in,
                              void* d_out, int out_size)
{
    const float* all_act = (const float*)d_in[0];
    const float* local_W = (const float*)d_in[1];
    const float* bias    = (const float*)d_in[2];
    float* out = (float*)d_out;

    init_flags<<<1, 256>>>();
    prep_W<<<dim3(NDIM / 32, KDIM / 32), dim3(32, 8)>>>(local_W);

    cudaFuncSetAttribute(ag_gemm_fused,
                         cudaFuncAttributeMaxDynamicSharedMemorySize, SMEM_TOTAL);
    dim3 grid(NDIM / BN, MDIM / BM);   // (8, 32) = 256 CTAs
    ag_gemm_fused<<<grid, NTH, SMEM_TOTAL>>>(all_act, bias, out);
}

// round 16
// speedup vs baseline: 1.1257x; 1.1257x over previous
#include <cuda_runtime.h>
#include <cuda_fp16.h>
#include <cstdint>
#include <cstddef>

// FusedAGGemm round 16: R12 champion GEMM (176.5us) + rebuilt prepass
// (warp-contiguous coalesced A convert, 64x64 W transpose tiles).
//   C[M,N] = sum_r A_r[M,KLOC] @ W[r*KLOC:(r+1)*KLOC] + bias

#define MDIM 4096
#define KLOC 1024
#define KDIM 8192
#define NDIM 1024
#define BM 128
#define BN 128
#define BK 64
#define NTH 256
#define NTILES (KDIM / BK)    // 128
#define NSTAGE 3

#define SWZ(o) ((o) ^ (((o) >> 3) & 0x70))
#define STAGE_BYTES 32768
#define SM_A(s) ((s) * STAGE_BYTES)
#define SM_B(s) ((s) * STAGE_BYTES + 16384)
#define SMEM_TOTAL (NSTAGE * STAGE_BYTES)

#define A_BLOCKS 4096
#define W_BLOCKS 2048

__device__ __half g_At[(size_t)MDIM * KDIM];   // 64 MB gathered fp16
__device__ __half g_Wt[(size_t)NDIM * KDIM];   // 16 MB W^T fp16

__device__ __forceinline__ uint32_t smem_u32(const void* p) {
    uint32_t a;
    asm("{ .reg .u64 t; cvta.to.shared.u64 t, %1; cvt.u32.u64 %0, t; }"
        : "=r"(a) : "l"(p));
    return a;
}
__device__ __forceinline__ uint32_t f16x2(float lo, float hi) {
    uint32_t r;
    asm("cvt.rn.f16x2.f32 %0, %2, %1;" : "=r"(r) : "f"(lo), "f"(hi));
    return r;
}
__device__ __forceinline__ void cp_async16(uint32_t dst, const void* src) {
    asm volatile("cp.async.cg.shared.global [%0], [%1], 16;"
                 :: "r"(dst), "l"(src) : "memory");
}
__device__ __forceinline__ void ldsm4(uint32_t addr, uint32_t* r) {
    asm volatile("ldmatrix.sync.aligned.m8n8.x4.shared.b16 {%0,%1,%2,%3}, [%4];"
                 : "=r"(r[0]), "=r"(r[1]), "=r"(r[2]), "=r"(r[3]) : "r"(addr));
}
__device__ __forceinline__ void mma_f16(float* c, const uint32_t* a,
                                        uint32_t b0, uint32_t b1) {
    asm volatile(
        "mma.sync.aligned.m16n8k16.row.col.f32.f16.f16.f32 "
        "{%0,%1,%2,%3}, {%4,%5,%6,%7}, {%8,%9}, {%0,%1,%2,%3};"
        : "+f"(c[0]), "+f"(c[1]), "+f"(c[2]), "+f"(c[3])
        : "r"(a[0]), "r"(a[1]), "r"(a[2]), "r"(a[3]), "r"(b0), "r"(b1));
}

// ---------------- fused prepass ----------------
// Blocks [0, A_BLOCKS): A gather+convert. One warp = 1024 contiguous halves
//   (exactly one shard-row segment). 8 coalesced LDG.128 (MLP=8) per lane.
// Blocks [A_BLOCKS, A_BLOCKS+W_BLOCKS): W transpose, 64x64 fp32 tiles.
__global__ void prep_all(const float* __restrict__ A, const float* __restrict__ W) {
    if (blockIdx.x < A_BLOCKS) {
        const int wg   = (blockIdx.x * NTH + threadIdx.x) >> 5;  // warp id [0,32768)
        const int lane = threadIdx.x & 31;
        const int m    = wg >> 3;          // row
        const int r    = wg & 7;           // shard == k-chunk
        const float* src = A + (((size_t)r * MDIM + m) << 10);
        __half* dst = g_At + ((size_t)m << 13) + ((size_t)r << 10);
        float4 v[8];
        #pragma unroll
        for (int j = 0; j < 8; ++j)       // 8 independent coalesced LDG.128
            v[j] = *reinterpret_cast<const float4*>(src + (j * 32 + lane) * 4);
        #pragma unroll
        for (int j = 0; j < 8; ++j) {
            uint2 o = { f16x2(v[j].x, v[j].y), f16x2(v[j].z, v[j].w) };
            *reinterpret_cast<uint2*>(dst + (j * 32 + lane) * 4) = o;
        }
    } else {
        __shared__ float t[64][65];
        const int b  = blockIdx.x - A_BLOCKS;     // 0..2047
        const int n0 = (b & 15) * 64;             // 16 n-tiles
        const int k0 = (b >> 4) * 64;             // 128 k-tiles
        const int col = threadIdx.x & 63;
        const int r0  = threadIdx.x >> 6;         // 0..3
        #pragma unroll
        for (int j = 0; j < 16; ++j)
            t[r0 + 4 * j][col] = W[(size_t)(k0 + r0 + 4 * j) * NDIM + n0 + col];
        __syncthreads();
        const int n  = threadIdx.x >> 2;          // 0..63
        const int ks = (threadIdx.x & 3) * 16;    // 0,16,32,48
        uint4 o0, o1;
        o0.x = f16x2(t[ks + 0][n],  t[ks + 1][n]);
        o0.y = f16x2(t[ks + 2][n],  t[ks + 3][n]);
        o0.z = f16x2(t[ks + 4][n],  t[ks + 5][n]);
        o0.w = f16x2(t[ks + 6][n],  t[ks + 7][n]);
        o1.x = f16x2(t[ks + 8][n],  t[ks + 9][n]);
        o1.y = f16x2(t[ks + 10][n], t[ks + 11][n]);
        o1.z = f16x2(t[ks + 12][n], t[ks + 13][n]);
        o1.w = f16x2(t[ks + 14][n], t[ks + 15][n]);
        __half* d = g_Wt + (size_t)(n0 + n) * KDIM + k0 + ks;
        *reinterpret_cast<uint4*>(d)     = o0;
        *reinterpret_cast<uint4*>(d + 8) = o1;
    }
}

// ---------------- main GEMM (R12 verbatim) ----------------
__global__ __launch_bounds__(NTH, 2)
void ag_gemm_mma(const float* __restrict__ bias, float* __restrict__ C)
{
    extern __shared__ char smem[];
    const uint32_t sb = smem_u32(smem);
    const int tid  = threadIdx.x;
    const int wid  = tid >> 5, lane = tid & 31;
    const int wm   = wid >> 2;
    const int wn   = wid & 3;
    const int m0   = blockIdx.y * BM;
    const int n0   = blockIdx.x * BN;

    const uint32_t rowA = (uint32_t)(wm * 64 + (lane & 15));
    const uint32_t kA16 = (uint32_t)((lane >> 4) * 16);
    const uint32_t rowB = (uint32_t)(wn * 32 + (lane & 7) + ((lane >> 4) << 3));
    const uint32_t kB16 = (uint32_t)(((lane >> 3) & 1) * 16);

    float acc[4][4][4];
    #pragma unroll
    for (int i = 0; i < 4; ++i)
        #pragma unroll
        for (int j = 0; j < 4; ++j)
            #pragma unroll
            for (int q = 0; q < 4; ++q) acc[i][j][q] = 0.0f;

    const int grow = tid >> 3;
    const int gcol = tid & 7;

    auto issue_tile = [&](int kt, int s) {
        const __half* Ab = g_At + (size_t)(m0 + grow) * KDIM + kt * BK + gcol * 8;
        const __half* Bb = g_Wt + (size_t)(n0 + grow) * KDIM + kt * BK + gcol * 8;
        #pragma unroll
        for (int i = 0; i < 4; ++i) {
            uint32_t o = SWZ((uint32_t)(grow + 32 * i) * 128u + (uint32_t)gcol * 16u);
            cp_async16(sb + SM_A(s) + o, Ab + (size_t)i * 32 * KDIM);
            cp_async16(sb + SM_B(s) + o, Bb + (size_t)i * 32 * KDIM);
        }
        asm volatile("cp.async.commit_group;" ::: "memory");
    };

    auto compute_tile = [&](int s) {
        #pragma unroll
        for (int k16 = 0; k16 < 4; ++k16) {
            uint32_t a[4][4], b[2][4];
            #pragma unroll
            for (int i = 0; i < 4; ++i) {
                uint32_t o = (rowA + 16u * i) * 128u + (uint32_t)k16 * 32u + kA16;
                ldsm4(sb + SM_A(s) + SWZ(o), a[i]);
            }
            #pragma unroll
            for (int j = 0; j < 2; ++j) {
                uint32_t o = (rowB + 16u * j) * 128u + (uint32_t)k16 * 32u + kB16;
                ldsm4(sb + SM_B(s) + SWZ(o), b[j]);
            }
            #pragma unroll
            for (int i = 0; i < 4; ++i) {
                #pragma unroll
                for (int jj = 0; jj < 4; ++jj)
                    mma_f16(acc[i][jj], a[i],
                            b[jj >> 1][(jj & 1) * 2], b[jj >> 1][(jj & 1) * 2 + 1]);
            }
        }
    };

    issue_tile(0, 0);
    issue_tile(1, 1);
    __syncthreads();

    for (int kt = 0; kt < NTILES; ++kt) {
        const int s = kt % NSTAGE;
        if (kt + 2 < NTILES) {
            issue_tile(kt + 2, (kt + 2) % NSTAGE);
            asm volatile("cp.async.wait_group 2;" ::: "memory");
        } else {
            asm volatile("cp.async.wait_group 0;" ::: "memory");
        }
        __syncthreads();
        compute_tile(s);
        __syncthreads();
    }

    const int er = lane >> 2;
    const int ec = (lane & 3) * 2;
    #pragma unroll
    for (int i = 0; i < 4; ++i) {
        const int gm = m0 + wm * 64 + i * 16 + er;
        #pragma unroll
        for (int jj = 0; jj < 4; ++jj) {
            const int gn = n0 + wn * 32 + jj * 8 + ec;
            const float bx = __ldg(bias + gn);
            const float by = __ldg(bias + gn + 1);
            float2 o0 = { acc[i][jj][0] + bx, acc[i][jj][1] + by };
            float2 o1 = { acc[i][jj][2] + bx, acc[i][jj][3] + by };
            *reinterpret_cast<float2*>(C + (size_t)gm * NDIM + gn) = o0;
            *reinterpret_cast<float2*>(C + (size_t)(gm + 8) * NDIM + gn) = o1;
        }
    }
}

extern "C" void kernel_launch(void* const* d_in, const int* in_sizes, int n_in,
                              void* d_out, int out_size)
{
    const float* all_act = (const float*)d_in[0];   // (8, 4096, 1024)
    const float* local_W = (const float*)d_in[1];   // (8192, 1024)
    const float* bias    = (const float*)d_in[2];   // (1024,)
    float* out = (float*)d_out;                     // (4096, 1024)

    prep_all<<<A_BLOCKS + W_BLOCKS, NTH>>>(all_act, local_W);

    cudaFuncSetAttribute(ag_gemm_mma,
                         cudaFuncAttributeMaxDynamicSharedMemorySize, SMEM_TOTAL);
    dim3 grid(NDIM / BN, MDIM / BM);   // (8, 32) = 256 CTAs
    ag_gemm_mma<<<grid, NTH, SMEM_TOTAL>>>(bias, out);
}